// round 6
// baseline (speedup 1.0000x reference)
#include <cuda_runtime.h>

#define H   8
#define LQ  384
#define LK  384
#define DQ  32
#define DV  32
#define DC  64
#define BS  2

#define K2 2.8853900817779268f   // 2*log2(e)
#define FLT_BIG 3.4e38f

// scratch: g_A[b,h,q,e] = exp(2*(q@W1_top + b1));  g_Ct[b,h,e,k] = exp(2*(k@W1_bot))
__device__ float g_A [BS * H * LQ * DC];
__device__ float g_Ct[BS * H * DC * LK];

__device__ __forceinline__ float ex2a(float x) {
    float r; asm("ex2.approx.f32 %0, %1;" : "=f"(r) : "f"(x)); return r;
}
__device__ __forceinline__ float rcpa(float x) {
    float r; asm("rcp.approx.f32 %0, %1;" : "=f"(r) : "f"(x)); return r;
}

// Tiled precompute: block = (bh, 128-row tile) for either the Q side or the K side.
// All GMEM traffic coalesced; math done from smem. Grid = 2 * BS*H*3 = 96 blocks.
__global__ void __launch_bounds__(256)
precompute(const float* __restrict__ q, const float* __restrict__ kin,
           const float* __restrict__ w1, const float* __restrict__ b1) {
    __shared__ float sX[128][DQ + 1];   // input rows (q or k), padded
    __shared__ float sW[DQ][DC];        // W1 half
    __shared__ float sB[DC];            // bias (Q side) or zeros

    int tid  = threadIdx.x;
    int bid  = blockIdx.x;
    int side = bid >= (BS * H * 3) ? 1 : 0;          // 0 = Q side, 1 = K side
    int loc  = bid - side * (BS * H * 3);
    int bh   = loc / 3;
    int tile = loc % 3;
    int h    = bh & (H - 1);
    int b    = bh >> 3;
    int rbase = tile * 128;

    const float* src = side ? kin : q;               // [b, L, H*32]
    // load 128 rows x 32 dims, coalesced (consecutive tid -> consecutive d)
    for (int i = tid; i < 128 * DQ; i += 256) {
        int r = i >> 5, d = i & 31;
        sX[r][d] = src[((size_t)(b * 384 + rbase + r)) * (H * DQ) + h * DQ + d];
    }
    // load W1 half: w1[h, side*DQ + d, e]
    for (int i = tid; i < DQ * DC; i += 256) {
        int d = i >> 6, e = i & 63;
        sW[d][e] = w1[h * DC * DC + (side * DQ + d) * DC + e];
    }
    if (tid < DC) sB[tid] = side ? 0.f : b1[h * DC + tid];
    __syncthreads();

    if (side == 0) {
        // outputs g_A[(bh*LQ + rbase + r)*DC + e]; o consecutive -> e fast (coalesced)
        for (int o = tid; o < 128 * DC; o += 256) {
            int r = o >> 6, e = o & 63;
            float acc = sB[e];
#pragma unroll
            for (int d = 0; d < DQ; d++) acc = fmaf(sX[r][d], sW[d][e], acc);
            g_A[((size_t)(bh * LQ + rbase + r)) * DC + e] = ex2a(K2 * acc);
        }
    } else {
        // outputs g_Ct[(bh*DC + e)*LK + rbase + kk]; o consecutive -> kk fast (coalesced)
        for (int o = tid; o < DC * 128; o += 256) {
            int e = o >> 7, kk = o & 127;
            float acc = 0.f;
#pragma unroll
            for (int d = 0; d < DQ; d++) acc = fmaf(sX[kk][d], sW[d][e], acc);
            g_Ct[((size_t)(bh * DC + e)) * LK + rbase + kk] = ex2a(K2 * acc);
        }
    }
}

// w0/d0 + w1/d1 = (w0*d1 + w1*d0) / (d0*d1): one rcp per TWO e-terms.
#define EPAIR(tax, tay, cx, cy, acc)                                   \
    {                                                                  \
        float d0_ = fmaf(tax, cx, 1.f), d1_ = fmaf(tay, cy, 1.f);      \
        float nu_ = fmaf(w.x, d1_, w.y * d0_);                         \
        acc = fmaf(nu_, rcpa(d0_ * d1_), acc);                         \
    }

// Block = 192 threads = 6 warps = 2 row-pairs x 3 k-chunks; 4 rows/block (same b,h).
__global__ void __launch_bounds__(192, 8)
attn_kernel(const float* __restrict__ w2, const float* __restrict__ v,
            const int* __restrict__ qlen, const int* __restrict__ klen,
            float* __restrict__ out, float* __restrict__ att) {
    __shared__ float sTA [4][DC];
    __shared__ float sW2 [DC];
    __shared__ float sP  [4][LK];
    __shared__ float sMn [4][3];
    __shared__ float sSum[4][3];
    __shared__ float sOut[4][3][DV];

    int tid  = threadIdx.x;
    int warp = tid >> 5;
    int lane = tid & 31;
    int rp    = (warp >= 3) ? 1 : 0;
    int chunk = warp - rp * 3;
    int rA = rp * 2, rB = rA + 1;

    int row0 = blockIdx.x * 4;
    int rowA = row0 + rA, rowB = row0 + rB;
    int bh   = row0 / LQ;
    int h    = bh & (H - 1);
    int b    = bh >> 3;

    for (int i = tid; i < 4 * DC; i += 192)
        sTA[i >> 6][i & 63] = g_A[(size_t)(row0 + (i >> 6)) * DC + (i & 63)];
    if (tid < DC) sW2[tid] = w2[h * DC + tid];
    __syncthreads();

    const int kl    = klen[b];
    const int kbase = chunk << 7;
    const float* ct = g_Ct + (size_t)bh * DC * LK;

    // ---- pass 1: 2 rows x 4 k per lane, e-pair combined ----
    float sa[4], sb[4];
    if (kbase < kl) {
        const float* cp = ct + kbase + lane * 4;
        float a0 = 0.f, a1 = 0.f, a2 = 0.f, a3 = 0.f;
        float b0 = 0.f, b1_ = 0.f, b2 = 0.f, b3 = 0.f;
#pragma unroll 8
        for (int ep = 0; ep < DC / 2; ep++) {
            float2 w  = *(const float2*)&sW2[2 * ep];
            float2 tA = *(const float2*)&sTA[rA][2 * ep];
            float2 tB = *(const float2*)&sTA[rB][2 * ep];
            float4 c0 = *(const float4*)(cp + (2 * ep) * LK);
            float4 c1 = *(const float4*)(cp + (2 * ep + 1) * LK);
            EPAIR(tA.x, tA.y, c0.x, c1.x, a0);
            EPAIR(tA.x, tA.y, c0.y, c1.y, a1);
            EPAIR(tA.x, tA.y, c0.z, c1.z, a2);
            EPAIR(tA.x, tA.y, c0.w, c1.w, a3);
            EPAIR(tB.x, tB.y, c0.x, c1.x, b0);
            EPAIR(tB.x, tB.y, c0.y, c1.y, b1_);
            EPAIR(tB.x, tB.y, c0.z, c1.z, b2);
            EPAIR(tB.x, tB.y, c0.w, c1.w, b3);
        }
        sa[0] = a0; sa[1] = a1; sa[2] = a2; sa[3] = a3;
        sb[0] = b0; sb[1] = b1_; sb[2] = b2; sb[3] = b3;
    } else {
#pragma unroll
        for (int j = 0; j < 4; j++) { sa[j] = FLT_BIG; sb[j] = FLT_BIG; }
    }

    // ---- min over valid k, block-combined ----
    float mnA = FLT_BIG, mnB = FLT_BIG;
#pragma unroll
    for (int j = 0; j < 4; j++) {
        if (kbase + lane * 4 + j < kl) {
            mnA = fminf(mnA, sa[j]);
            mnB = fminf(mnB, sb[j]);
        }
    }
#pragma unroll
    for (int o = 16; o; o >>= 1) {
        mnA = fminf(mnA, __shfl_xor_sync(0xffffffffu, mnA, o));
        mnB = fminf(mnB, __shfl_xor_sync(0xffffffffu, mnB, o));
    }
    if (lane == 0) { sMn[rA][chunk] = mnA; sMn[rB][chunk] = mnB; }
    __syncthreads();
    mnA = fminf(fminf(sMn[rA][0], sMn[rA][1]), sMn[rA][2]);
    mnB = fminf(fminf(sMn[rB][0], sMn[rB][1]), sMn[rB][2]);

    // ---- pass 2: probs + sums ----
    float pA[4], pB[4];
    float sumA = 0.f, sumB = 0.f;
#pragma unroll
    for (int j = 0; j < 4; j++) {
        int kk = kbase + lane * 4 + j;
        float pa = (kk < kl) ? ex2a(K2 * (mnA - sa[j])) : 0.f;
        float pb = (kk < kl) ? ex2a(K2 * (mnB - sb[j])) : 0.f;
        pA[j] = pa; pB[j] = pb;
        sumA += pa; sumB += pb;
    }
#pragma unroll
    for (int o = 16; o; o >>= 1) {
        sumA += __shfl_xor_sync(0xffffffffu, sumA, o);
        sumB += __shfl_xor_sync(0xffffffffu, sumB, o);
    }
    if (lane == 0) { sSum[rA][chunk] = sumA; sSum[rB][chunk] = sumB; }
    *(float4*)&sP[rA][kbase + lane * 4] = make_float4(pA[0], pA[1], pA[2], pA[3]);
    *(float4*)&sP[rB][kbase + lane * 4] = make_float4(pB[0], pB[1], pB[2], pB[3]);
    __syncthreads();

    float rinvA = 1.0f / ((sSum[rA][0] + sSum[rA][1]) + sSum[rA][2]);
    float rinvB = 1.0f / ((sSum[rB][0] + sSum[rB][1]) + sSum[rB][2]);

    *(float4*)(att + (size_t)rowA * LK + kbase + lane * 4) =
        make_float4(pA[0] * rinvA, pA[1] * rinvA, pA[2] * rinvA, pA[3] * rinvA);
    *(float4*)(att + (size_t)rowB * LK + kbase + lane * 4) =
        make_float4(pB[0] * rinvB, pB[1] * rinvB, pB[2] * rinvB, pB[3] * rinvB);

    // ---- AV: lane -> (kg, dv4); float4 v loads shared by the 2 rows ----
    int kg  = lane >> 3;
    int dv4 = (lane & 7) << 2;
    float4 oA = make_float4(0.f, 0.f, 0.f, 0.f);
    float4 oB = make_float4(0.f, 0.f, 0.f, 0.f);
    int kcap = kl - kbase; if (kcap > 128) kcap = 128;
    const float* vb = v + ((size_t)(b * LK + kbase + kg)) * (H * DV) + h * DV + dv4;
#pragma unroll 4
    for (int kk = kg; kk < kcap; kk += 4, vb += 4 * (H * DV)) {
        float4 vv = *(const float4*)vb;
        float pa = sP[rA][kbase + kk];
        float pb = sP[rB][kbase + kk];
        oA.x = fmaf(pa, vv.x, oA.x); oA.y = fmaf(pa, vv.y, oA.y);
        oA.z = fmaf(pa, vv.z, oA.z); oA.w = fmaf(pa, vv.w, oA.w);
        oB.x = fmaf(pb, vv.x, oB.x); oB.y = fmaf(pb, vv.y, oB.y);
        oB.z = fmaf(pb, vv.z, oB.z); oB.w = fmaf(pb, vv.w, oB.w);
    }
#pragma unroll
    for (int o = 8; o <= 16; o <<= 1) {
        oA.x += __shfl_xor_sync(0xffffffffu, oA.x, o);
        oA.y += __shfl_xor_sync(0xffffffffu, oA.y, o);
        oA.z += __shfl_xor_sync(0xffffffffu, oA.z, o);
        oA.w += __shfl_xor_sync(0xffffffffu, oA.w, o);
        oB.x += __shfl_xor_sync(0xffffffffu, oB.x, o);
        oB.y += __shfl_xor_sync(0xffffffffu, oB.y, o);
        oB.z += __shfl_xor_sync(0xffffffffu, oB.z, o);
        oB.w += __shfl_xor_sync(0xffffffffu, oB.w, o);
    }
    if (kg == 0) {
        *(float4*)&sOut[rA][chunk][dv4] = oA;
        *(float4*)&sOut[rB][chunk][dv4] = oB;
    }
    __syncthreads();

    if (chunk == 0) {
        const int ql = qlen[b];
        float ooA = ((sOut[rA][0][lane] + sOut[rA][1][lane]) + sOut[rA][2][lane]) * rinvA;
        float ooB = ((sOut[rB][0][lane] + sOut[rB][1][lane]) + sOut[rB][2][lane]) * rinvB;
        int qiA = rowA - bh * LQ;
        int qiB = rowB - bh * LQ;
        if (qiA >= ql) ooA = 0.f;
        if (qiB >= ql) ooB = 0.f;
        out[((size_t)(b * LQ + qiA)) * (H * DV) + h * DV + lane] = ooA;
        out[((size_t)(b * LQ + qiB)) * (H * DV) + h * DV + lane] = ooB;
    }
}

extern "C" void kernel_launch(void* const* d_in, const int* in_sizes, int n_in,
                              void* d_out, int out_size) {
    const float* q    = (const float*)d_in[0];
    const float* k    = (const float*)d_in[1];
    const float* v    = (const float*)d_in[2];
    const int*   qlen = (const int*)  d_in[3];
    const int*   klen = (const int*)  d_in[4];
    const float* w1   = (const float*)d_in[5];
    const float* b1   = (const float*)d_in[6];
    const float* w2   = (const float*)d_in[7];

    float* out = (float*)d_out;
    float* att = out + (size_t)BS * LQ * H * DV;

    precompute<<<2 * BS * H * 3, 256>>>(q, k, w1, b1);
    attn_kernel<<<(BS * H * LQ) / 4, 192>>>(w2, v, qlen, klen, out, att);
}

// round 7
// speedup vs baseline: 1.5332x; 1.5332x over previous
#include <cuda_runtime.h>

#define H   8
#define LQ  384
#define LK  384
#define DQ  32
#define DV  32
#define DC  64
#define BS  2

#define K2 2.8853900817779268f   // 2*log2(e)
#define FLT_BIG 3.4e38f

// scratch: g_A[b,h,q,e] = exp(2*(q@W1_top + b1));  g_Ct[b,h,e,k] = exp(2*(k@W1_bot))
__device__ float g_A [BS * H * LQ * DC];
__device__ float g_Ct[BS * H * DC * LK];

__device__ __forceinline__ float ex2a(float x) {
    float r; asm("ex2.approx.f32 %0, %1;" : "=f"(r) : "f"(x)); return r;
}
__device__ __forceinline__ float rcpa(float x) {
    float r; asm("rcp.approx.f32 %0, %1;" : "=f"(r) : "f"(x)); return r;
}

// Tiled precompute: block = (bh, 128-row tile) for either the Q side or the K side.
// All GMEM traffic coalesced; math done from smem. Grid = 2 * BS*H*3 = 96 blocks.
__global__ void __launch_bounds__(256)
precompute(const float* __restrict__ q, const float* __restrict__ kin,
           const float* __restrict__ w1, const float* __restrict__ b1) {
    __shared__ float sX[128][DQ + 1];   // input rows (q or k), padded
    __shared__ float sW[DQ][DC];        // W1 half
    __shared__ float sB[DC];            // bias (Q side) or zeros

    int tid  = threadIdx.x;
    int bid  = blockIdx.x;
    int side = bid >= (BS * H * 3) ? 1 : 0;          // 0 = Q side, 1 = K side
    int loc  = bid - side * (BS * H * 3);
    int bh   = loc / 3;
    int tile = loc % 3;
    int h    = bh & (H - 1);
    int b    = bh >> 3;
    int rbase = tile * 128;

    const float* src = side ? kin : q;               // [b, L, H*32]
    for (int i = tid; i < 128 * DQ; i += 256) {
        int r = i >> 5, d = i & 31;
        sX[r][d] = src[((size_t)(b * 384 + rbase + r)) * (H * DQ) + h * DQ + d];
    }
    for (int i = tid; i < DQ * DC; i += 256) {
        int d = i >> 6, e = i & 63;
        sW[d][e] = w1[h * DC * DC + (side * DQ + d) * DC + e];
    }
    if (tid < DC) sB[tid] = side ? 0.f : b1[h * DC + tid];
    __syncthreads();

    if (side == 0) {
        for (int o = tid; o < 128 * DC; o += 256) {
            int r = o >> 6, e = o & 63;
            float acc = sB[e];
#pragma unroll
            for (int d = 0; d < DQ; d++) acc = fmaf(sX[r][d], sW[d][e], acc);
            g_A[((size_t)(bh * LQ + rbase + r)) * DC + e] = ex2a(K2 * acc);
        }
    } else {
        for (int o = tid; o < DC * 128; o += 256) {
            int e = o >> 7, kk = o & 127;
            float acc = 0.f;
#pragma unroll
            for (int d = 0; d < DQ; d++) acc = fmaf(sX[kk][d], sW[d][e], acc);
            g_Ct[((size_t)(bh * DC + e)) * LK + rbase + kk] = ex2a(K2 * acc);
        }
    }
}

// w0/d0 + w1/d1 = (w0*d1 + w1*d0) / (d0*d1): one rcp per TWO e-terms.
#define EPAIR(tax, tay, cx, cy, acc)                                   \
    {                                                                  \
        float d0_ = fmaf(tax, cx, 1.f), d1_ = fmaf(tay, cy, 1.f);      \
        float nu_ = fmaf(w.x, d1_, w.y * d0_);                         \
        acc = fmaf(nu_, rcpa(d0_ * d1_), acc);                         \
    }

// Block = 192 threads = 6 warps = 2 row-pairs x 3 k-chunks; 4 rows/block (same b,h).
// NOTE: no min-blocks clause — R6 showed capping regs to 40 costs 42% runtime.
__global__ void __launch_bounds__(192)
attn_kernel(const float* __restrict__ w2, const float* __restrict__ v,
            const int* __restrict__ qlen, const int* __restrict__ klen,
            float* __restrict__ out, float* __restrict__ att) {
    __shared__ float sTA [4][DC];
    __shared__ float sW2 [DC];
    __shared__ float sP  [4][LK];
    __shared__ float sMn [4][3];
    __shared__ float sSum[4][3];
    __shared__ float sOut[4][3][DV];

    int tid  = threadIdx.x;
    int warp = tid >> 5;
    int lane = tid & 31;
    int rp    = (warp >= 3) ? 1 : 0;
    int chunk = warp - rp * 3;
    int rA = rp * 2, rB = rA + 1;

    int row0 = blockIdx.x * 4;
    int rowA = row0 + rA, rowB = row0 + rB;
    int bh   = row0 / LQ;
    int h    = bh & (H - 1);
    int b    = bh >> 3;

    for (int i = tid; i < 4 * DC; i += 192)
        sTA[i >> 6][i & 63] = g_A[(size_t)(row0 + (i >> 6)) * DC + (i & 63)];
    if (tid < DC) sW2[tid] = w2[h * DC + tid];
    __syncthreads();

    const int kl    = klen[b];
    const int kbase = chunk << 7;
    const float* ct = g_Ct + (size_t)bh * DC * LK;

    // ---- pass 1: 2 rows x 4 k per lane, e-pair combined ----
    float sa[4], sb[4];
    if (kbase < kl) {
        const float* cp = ct + kbase + lane * 4;
        float a0 = 0.f, a1 = 0.f, a2 = 0.f, a3 = 0.f;
        float b0 = 0.f, b1_ = 0.f, b2 = 0.f, b3 = 0.f;
#pragma unroll 8
        for (int ep = 0; ep < DC / 2; ep++) {
            float2 w  = *(const float2*)&sW2[2 * ep];
            float2 tA = *(const float2*)&sTA[rA][2 * ep];
            float2 tB = *(const float2*)&sTA[rB][2 * ep];
            float4 c0 = *(const float4*)(cp + (2 * ep) * LK);
            float4 c1 = *(const float4*)(cp + (2 * ep + 1) * LK);
            EPAIR(tA.x, tA.y, c0.x, c1.x, a0);
            EPAIR(tA.x, tA.y, c0.y, c1.y, a1);
            EPAIR(tA.x, tA.y, c0.z, c1.z, a2);
            EPAIR(tA.x, tA.y, c0.w, c1.w, a3);
            EPAIR(tB.x, tB.y, c0.x, c1.x, b0);
            EPAIR(tB.x, tB.y, c0.y, c1.y, b1_);
            EPAIR(tB.x, tB.y, c0.z, c1.z, b2);
            EPAIR(tB.x, tB.y, c0.w, c1.w, b3);
        }
        sa[0] = a0; sa[1] = a1; sa[2] = a2; sa[3] = a3;
        sb[0] = b0; sb[1] = b1_; sb[2] = b2; sb[3] = b3;
    } else {
#pragma unroll
        for (int j = 0; j < 4; j++) { sa[j] = FLT_BIG; sb[j] = FLT_BIG; }
    }

    // ---- min over valid k, block-combined ----
    float mnA = FLT_BIG, mnB = FLT_BIG;
#pragma unroll
    for (int j = 0; j < 4; j++) {
        if (kbase + lane * 4 + j < kl) {
            mnA = fminf(mnA, sa[j]);
            mnB = fminf(mnB, sb[j]);
        }
    }
#pragma unroll
    for (int o = 16; o; o >>= 1) {
        mnA = fminf(mnA, __shfl_xor_sync(0xffffffffu, mnA, o));
        mnB = fminf(mnB, __shfl_xor_sync(0xffffffffu, mnB, o));
    }
    if (lane == 0) { sMn[rA][chunk] = mnA; sMn[rB][chunk] = mnB; }
    __syncthreads();
    mnA = fminf(fminf(sMn[rA][0], sMn[rA][1]), sMn[rA][2]);
    mnB = fminf(fminf(sMn[rB][0], sMn[rB][1]), sMn[rB][2]);

    // ---- pass 2: probs + sums ----
    float pA[4], pB[4];
    float sumA = 0.f, sumB = 0.f;
#pragma unroll
    for (int j = 0; j < 4; j++) {
        int kk = kbase + lane * 4 + j;
        float pa = (kk < kl) ? ex2a(K2 * (mnA - sa[j])) : 0.f;
        float pb = (kk < kl) ? ex2a(K2 * (mnB - sb[j])) : 0.f;
        pA[j] = pa; pB[j] = pb;
        sumA += pa; sumB += pb;
    }
#pragma unroll
    for (int o = 16; o; o >>= 1) {
        sumA += __shfl_xor_sync(0xffffffffu, sumA, o);
        sumB += __shfl_xor_sync(0xffffffffu, sumB, o);
    }
    if (lane == 0) { sSum[rA][chunk] = sumA; sSum[rB][chunk] = sumB; }
    *(float4*)&sP[rA][kbase + lane * 4] = make_float4(pA[0], pA[1], pA[2], pA[3]);
    *(float4*)&sP[rB][kbase + lane * 4] = make_float4(pB[0], pB[1], pB[2], pB[3]);
    __syncthreads();

    float rinvA = 1.0f / ((sSum[rA][0] + sSum[rA][1]) + sSum[rA][2]);
    float rinvB = 1.0f / ((sSum[rB][0] + sSum[rB][1]) + sSum[rB][2]);

    *(float4*)(att + (size_t)rowA * LK + kbase + lane * 4) =
        make_float4(pA[0] * rinvA, pA[1] * rinvA, pA[2] * rinvA, pA[3] * rinvA);
    *(float4*)(att + (size_t)rowB * LK + kbase + lane * 4) =
        make_float4(pB[0] * rinvB, pB[1] * rinvB, pB[2] * rinvB, pB[3] * rinvB);

    // ---- AV: lane -> (kg, dv4); float4 v loads shared by the 2 rows ----
    int kg  = lane >> 3;
    int dv4 = (lane & 7) << 2;
    float4 oA = make_float4(0.f, 0.f, 0.f, 0.f);
    float4 oB = make_float4(0.f, 0.f, 0.f, 0.f);
    int kcap = kl - kbase; if (kcap > 128) kcap = 128;
    const float* vb = v + ((size_t)(b * LK + kbase + kg)) * (H * DV) + h * DV + dv4;
    for (int kk = kg; kk < kcap; kk += 4, vb += 4 * (H * DV)) {
        float4 vv = *(const float4*)vb;
        float pa = sP[rA][kbase + kk];
        float pb = sP[rB][kbase + kk];
        oA.x = fmaf(pa, vv.x, oA.x); oA.y = fmaf(pa, vv.y, oA.y);
        oA.z = fmaf(pa, vv.z, oA.z); oA.w = fmaf(pa, vv.w, oA.w);
        oB.x = fmaf(pb, vv.x, oB.x); oB.y = fmaf(pb, vv.y, oB.y);
        oB.z = fmaf(pb, vv.z, oB.z); oB.w = fmaf(pb, vv.w, oB.w);
    }
#pragma unroll
    for (int o = 8; o <= 16; o <<= 1) {
        oA.x += __shfl_xor_sync(0xffffffffu, oA.x, o);
        oA.y += __shfl_xor_sync(0xffffffffu, oA.y, o);
        oA.z += __shfl_xor_sync(0xffffffffu, oA.z, o);
        oA.w += __shfl_xor_sync(0xffffffffu, oA.w, o);
        oB.x += __shfl_xor_sync(0xffffffffu, oB.x, o);
        oB.y += __shfl_xor_sync(0xffffffffu, oB.y, o);
        oB.z += __shfl_xor_sync(0xffffffffu, oB.z, o);
        oB.w += __shfl_xor_sync(0xffffffffu, oB.w, o);
    }
    if (kg == 0) {
        *(float4*)&sOut[rA][chunk][dv4] = oA;
        *(float4*)&sOut[rB][chunk][dv4] = oB;
    }
    __syncthreads();

    if (chunk == 0) {
        const int ql = qlen[b];
        float ooA = ((sOut[rA][0][lane] + sOut[rA][1][lane]) + sOut[rA][2][lane]) * rinvA;
        float ooB = ((sOut[rB][0][lane] + sOut[rB][1][lane]) + sOut[rB][2][lane]) * rinvB;
        int qiA = rowA - bh * LQ;
        int qiB = rowB - bh * LQ;
        if (qiA >= ql) ooA = 0.f;
        if (qiB >= ql) ooB = 0.f;
        out[((size_t)(b * LQ + qiA)) * (H * DV) + h * DV + lane] = ooA;
        out[((size_t)(b * LQ + qiB)) * (H * DV) + h * DV + lane] = ooB;
    }
}

extern "C" void kernel_launch(void* const* d_in, const int* in_sizes, int n_in,
                              void* d_out, int out_size) {
    const float* q    = (const float*)d_in[0];
    const float* k    = (const float*)d_in[1];
    const float* v    = (const float*)d_in[2];
    const int*   qlen = (const int*)  d_in[3];
    const int*   klen = (const int*)  d_in[4];
    const float* w1   = (const float*)d_in[5];
    const float* b1   = (const float*)d_in[6];
    const float* w2   = (const float*)d_in[7];

    float* out = (float*)d_out;
    float* att = out + (size_t)BS * LQ * H * DV;

    precompute<<<2 * BS * H * 3, 256>>>(q, k, w1, b1);
    attn_kernel<<<(BS * H * LQ) / 4, 192>>>(w2, v, qlen, klen, out, att);
}